// round 5
// baseline (speedup 1.0000x reference)
#include <cuda_runtime.h>
#include <cuda_bf16.h>
#include <cstdint>

// Only Z0[:,:,-1] = conv(X0, t=10) is nonzero in the output.
// Needs: h3 rows t=9,10 ; U feats 9,10,11 ; 3 adjacencies (a=10,9,11 ; c=10).
// Softmax degree-normalization in norm_adj is an exact no-op.
//
// 2-node graph: mega_kernel (persistent, phased with grid barriers) + conv_kernel.

#define NBLK 148
#define NTHR 256
#define NT (NBLK * NTHR)
#define NW (NBLK * 8)

// ---------------- device scratch ----------------
__device__ float g_obs2[2 * 8192];     // MLP input rows t=9,10
__device__ float g_s1[2 * 2048];       // bias-init, gemv1 accumulates (pre-relu)
__device__ float g_s2[2 * 2048];
__device__ float g_s3[2 * 12288];      // row0 = X9 pre-relu, row1 = X10 pre-relu
__device__ float g_sph[12 * 256];      // hidden (pre-relu)
__device__ float g_tph[256];           // hidden (pre-relu)
__device__ float g_U[3 * 1024 * 12];   // [c][n][tau], c = feat-9 (post-activation)
__device__ float g_Y[1024 * 12];       // Y[n][p] = sum_q B[p,q]*U[n,q,10]

// ---------------- grid barrier (sense-reversing, replay-safe) --------------
__device__ unsigned g_bar_cnt[4];      // zero-init; releaser resets
__device__ unsigned g_bar_flag[4];     // persistent sense; re-read each run

__device__ __forceinline__ void grid_barrier(int i) {
    __syncthreads();
    if (threadIdx.x == 0) {
        volatile unsigned* fl = &g_bar_flag[i];
        unsigned sense = *fl;          // read BEFORE arriving
        __threadfence();
        unsigned old = atomicAdd(&g_bar_cnt[i], 1);
        if (old == NBLK - 1) {
            g_bar_cnt[i] = 0;          // reset for next replay
            __threadfence();
            *fl = sense ^ 1u;          // release
        } else {
            while (*fl == sense) { }
        }
        __threadfence();
    }
    __syncthreads();
}

// ---------------- gemv tile: M=2 rows, 4 cols, len-K chunk -----------------
template<int K, int N, bool RELU>
__device__ __forceinline__ void gemv_tile(const float* __restrict__ A,
                                          const float* __restrict__ W,
                                          float* __restrict__ S,
                                          int col, int k0, int len) {
    float a00 = 0, a01 = 0, a02 = 0, a03 = 0;
    float a10 = 0, a11 = 0, a12 = 0, a13 = 0;
#pragma unroll 8
    for (int k = k0; k < k0 + len; ++k) {
        const float4 w = *reinterpret_cast<const float4*>(W + (size_t)k * N + col);
        float x0 = A[k], x1 = A[K + k];
        if (RELU) { x0 = fmaxf(x0, 0.0f); x1 = fmaxf(x1, 0.0f); }
        a00 += x0 * w.x; a01 += x0 * w.y; a02 += x0 * w.z; a03 += x0 * w.w;
        a10 += x1 * w.x; a11 += x1 * w.y; a12 += x1 * w.z; a13 += x1 * w.w;
    }
    atomicAdd(S + col + 0, a00); atomicAdd(S + col + 1, a01);
    atomicAdd(S + col + 2, a02); atomicAdd(S + col + 3, a03);
    atomicAdd(S + N + col + 0, a10); atomicAdd(S + N + col + 1, a11);
    atomicAdd(S + N + col + 2, a12); atomicAdd(S + N + col + 3, a13);
}

// ---------------- persistent mega kernel ----------------
__global__ void __launch_bounds__(NTHR, 1)
mega_kernel(const float* __restrict__ obs,
            const float* __restrict__ tf,
            const float* __restrict__ fc_w1, const float* __restrict__ b1,
            const float* __restrict__ fc_w2, const float* __restrict__ b2,
            const float* __restrict__ fc_w3, const float* __restrict__ b3,
            const float* __restrict__ li,
            const float* __restrict__ gs_w1, const float* __restrict__ gs_b1,
            const float* __restrict__ gs_w2, const float* __restrict__ gs_b2,
            const float* __restrict__ gt_w1, const float* __restrict__ gt_b1,
            const float* __restrict__ gt_w2, const float* __restrict__ gt_b2,
            const float* __restrict__ Bm,
            float* __restrict__ out) {
    const int tid = threadIdx.x, bid = blockIdx.x;
    const int gthread = bid * NTHR + tid;
    const int gwarp = gthread >> 5;
    const int lane = tid & 31;

    // ======== P0a: gathers + bias inits + out-tail zero (thread-stride) ====
    for (int idx = gthread; idx < 86016; idx += NT) {
        int i = idx;
        if (i < 16384) {
            int m = i >> 13, k = i & 8191;
            int n = k >> 3, d = k & 7;
            g_obs2[i] = obs[n * 96 + d * 12 + 9 + m];
            continue;
        }
        i -= 16384;
        if (i < 4096)  { g_s1[i] = b1[i & 2047]; continue; }
        i -= 4096;
        if (i < 4096)  { g_s2[i] = b2[i & 2047]; continue; }
        i -= 4096;
        if (i < 24576) { g_s3[i] = b3[i % 12288]; continue; }
        i -= 24576;
        out[12288 + i] = 0.0f;                       // zero Z1..Z3 outputs
    }
    // ======== P0b: sph (12x256) + tph (256) as warp tasks ==================
    for (int w = gwarp; w < 3072 + 8; w += NW) {
        if (w < 3072) {
            int tau = w >> 8, t = w & 255;
            const float* row  = li + tau * 1024;
            const float* wcol = gs_w1 + t;
            float acc = 0.0f;
#pragma unroll 8
            for (int k = lane; k < 1024; k += 32)
                acc += row[k] * wcol[(size_t)k * 256];
#pragma unroll
            for (int o = 16; o; o >>= 1) acc += __shfl_xor_sync(0xffffffffu, acc, o);
            if (lane == 0) g_sph[tau * 256 + t] = acc + gs_b1[t];
        } else {
            int t = (w - 3072) * 32 + lane;
            float acc = 0.0f;
#pragma unroll
            for (int k = 0; k < 36; ++k) acc += tf[k] * gt_w1[k * 256 + t];
            g_tph[t] = acc + gt_b1[t];
        }
    }
    grid_barrier(0);

    // ======== P1: blocks 0..39 -> fused u+y ; blocks 40..147 -> gemv1 ======
    if (bid < 40) {
        int lw = bid * 8 + (tid >> 5);               // 0..319
        for (int task = lw; task < 3072; task += 320) {
            int n = task / 3, c = task - n * 3;      // c: 0..2 -> feats 9..11
            int j = n * 12 + 9 + c;
            float wg[8], wt[8];
#pragma unroll
            for (int i = 0; i < 8; ++i) {
                int k = lane + 32 * i;
                wg[i] = gs_w2[(size_t)k * 12288 + j];
                wt[i] = gt_w2[(size_t)k * 12288 + j];
            }
            float tp = 0.0f;
#pragma unroll
            for (int i = 0; i < 8; ++i)
                tp += fmaxf(g_tph[lane + 32 * i], 0.0f) * wt[i];
#pragma unroll
            for (int o = 16; o; o >>= 1) tp += __shfl_xor_sync(0xffffffffu, tp, o);
            float tpv = fmaxf(tp + gt_b2[j], 0.0f);
            float bsp = gs_b2[j];

            float bm[12];
            bool doy = (c == 1);
            if (doy && lane < 12) {
#pragma unroll
                for (int q = 0; q < 12; ++q) bm[q] = Bm[lane * 12 + q];
            } else {
#pragma unroll
                for (int q = 0; q < 12; ++q) bm[q] = 0.0f;
            }
            float yacc = 0.0f;
#pragma unroll
            for (int tau = 0; tau < 12; ++tau) {
                float sp = 0.0f;
#pragma unroll
                for (int i = 0; i < 8; ++i)
                    sp += fmaxf(g_sph[tau * 256 + lane + 32 * i], 0.0f) * wg[i];
#pragma unroll
                for (int o = 16; o; o >>= 1) sp += __shfl_xor_sync(0xffffffffu, sp, o);
                float v = fmaxf(sp + bsp, 0.0f) + tpv;   // all lanes hold v
                if (lane == (tau & 31)) g_U[c * 12288 + n * 12 + tau] = v;
                yacc += bm[tau] * v;
            }
            if (doy && lane < 12) g_Y[n * 12 + lane] = yacc;
        }
    } else {
        int lt = (bid - 40) * NTHR + tid;            // 0..27647
        for (int tile = lt; tile < 512 * 64; tile += 108 * NTHR) {
            int col4 = tile & 511, kc = tile >> 9;   // 64 chunks of 128
            gemv_tile<8192, 2048, false>(g_obs2, fc_w1, g_s1, col4 * 4, kc * 128, 128);
        }
    }
    grid_barrier(1);

    // ======== P2: gemv2 (all blocks), 512 col4 x 64 chunks of 32 ===========
    for (int tile = gthread; tile < 512 * 64; tile += NT) {
        int col4 = tile & 511, kc = tile >> 9;
        gemv_tile<2048, 2048, true>(g_s1, fc_w2, g_s2, col4 * 4, kc * 32, 32);
    }
    grid_barrier(2);

    // ======== P3: gemv3 (all blocks), 3072 col4 x 16 chunks of 128 =========
    for (int tile = gthread; tile < 3072 * 16; tile += NT) {
        int col4 = tile % 3072, kc = tile / 3072;
        gemv_tile<2048, 12288, true>(g_s2, fc_w3, g_s3, col4 * 4, kc * 128, 128);
    }
}

// ---------------- fused conv: adjacency softmax + SpMM + combine -----------
#define C_SY    0
#define C_SX10  12288
#define C_SX9   24576
#define C_SU    36864      // 8 rows * 3 feats * 12 = 288
#define C_SW    37152      // 144 W0sum | 144 Wf1 | 144 Wb1 | 12 b
#define C_SRED  37600      // 256 * 27
#define C_SRED2 44512      // 8 * 26
#define C_SACC  44720      // 3 * 26
#define C_SMEM_FLOATS 44800

__device__ __forceinline__ float4 relu4(float4 v) {
    v.x = fmaxf(v.x, 0.0f); v.y = fmaxf(v.y, 0.0f);
    v.z = fmaxf(v.z, 0.0f); v.w = fmaxf(v.w, 0.0f);
    return v;
}

__global__ void __launch_bounds__(256, 1)
conv_kernel(const float* __restrict__ Wf, const float* __restrict__ Wb,
            const float* __restrict__ bvec, float* __restrict__ out) {
    extern __shared__ float sm[];
    float* sY   = sm + C_SY;
    float* sX10 = sm + C_SX10;
    float* sX9  = sm + C_SX9;
    float* sU   = sm + C_SU;
    float* sW   = sm + C_SW;
    float* sRED = sm + C_SRED;
    float* sRED2= sm + C_SRED2;
    float* sACC = sm + C_SACC;

    int tid = threadIdx.x;
    int rowbase = blockIdx.x * 8;

    for (int i = tid; i < 12288 / 4; i += 256) {
        ((float4*)sY)[i]   = ((const float4*)g_Y)[i];
        ((float4*)sX10)[i] = relu4(((const float4*)(g_s3 + 12288))[i]);
        ((float4*)sX9)[i]  = relu4(((const float4*)g_s3)[i]);
    }
    for (int i = tid; i < 288; i += 256) {
        int r = i / 36, rem = i % 36;
        int c = rem / 12, tau = rem % 12;
        sU[i] = g_U[c * 12288 + (rowbase + r) * 12 + tau];
    }
    if (tid < 144) {
        sW[tid]       = Wf[tid] + Wb[tid];   // k=0: Wf0+Wb0
        sW[144 + tid] = Wf[144 + tid];       // Wf1
        sW[288 + tid] = Wb[144 + tid];       // Wb1
    }
    if (tid < 12) sW[432 + tid] = bvec[tid];
    __syncthreads();

    for (int tile = 0; tile < 4; ++tile) {
        int r0 = tile * 2;
        for (int ap = 0; ap < 3; ++ap) {
            int cidx = (ap == 0) ? 1 : (ap == 1 ? 0 : 2); // a = 10, 9, 11
            const float* sX = (ap == 0) ? sX10 : sX9;
            float u0[12], u1[12];
#pragma unroll
            for (int q = 0; q < 12; ++q) {
                u0[q] = sU[(r0 * 3 + cidx) * 12 + q];
                u1[q] = sU[((r0 + 1) * 3 + cidx) * 12 + q];
            }
            float g0[12], g1[12];
#pragma unroll
            for (int q = 0; q < 12; ++q) { g0[q] = 0.0f; g1[q] = 0.0f; }
            float es0 = 0.0f, es1 = 0.0f;

            for (int j = tid; j < 1024; j += 256) {
                const float4* yr = (const float4*)(sY + j * 12);
                float4 ya = yr[0], yb = yr[1], yc = yr[2];
                float s0 = u0[0]*ya.x + u0[1]*ya.y + u0[2]*ya.z + u0[3]*ya.w
                         + u0[4]*yb.x + u0[5]*yb.y + u0[6]*yb.z + u0[7]*yb.w
                         + u0[8]*yc.x + u0[9]*yc.y + u0[10]*yc.z + u0[11]*yc.w;
                float s1 = u1[0]*ya.x + u1[1]*ya.y + u1[2]*ya.z + u1[3]*ya.w
                         + u1[4]*yb.x + u1[5]*yb.y + u1[6]*yb.z + u1[7]*yb.w
                         + u1[8]*yc.x + u1[9]*yc.y + u1[10]*yc.z + u1[11]*yc.w;
                s0 = (s0 >= 0.05f) ? s0 : 0.0f;
                s1 = (s1 >= 0.05f) ? s1 : 0.0f;
                float e0 = __expf(s0), e1 = __expf(s1);
                es0 += e0; es1 += e1;
                const float4* xr = (const float4*)(sX + j * 12);
                float4 xa = xr[0], xb = xr[1], xc = xr[2];
                g0[0]+=e0*xa.x; g0[1]+=e0*xa.y; g0[2] +=e0*xa.z; g0[3] +=e0*xa.w;
                g0[4]+=e0*xb.x; g0[5]+=e0*xb.y; g0[6] +=e0*xb.z; g0[7] +=e0*xb.w;
                g0[8]+=e0*xc.x; g0[9]+=e0*xc.y; g0[10]+=e0*xc.z; g0[11]+=e0*xc.w;
                g1[0]+=e1*xa.x; g1[1]+=e1*xa.y; g1[2] +=e1*xa.z; g1[3] +=e1*xa.w;
                g1[4]+=e1*xb.x; g1[5]+=e1*xb.y; g1[6] +=e1*xb.z; g1[7] +=e1*xb.w;
                g1[8]+=e1*xc.x; g1[9]+=e1*xc.y; g1[10]+=e1*xc.z; g1[11]+=e1*xc.w;
            }
#pragma unroll
            for (int q = 0; q < 12; ++q) {
                sRED[tid * 27 + q]      = g0[q];
                sRED[tid * 27 + 13 + q] = g1[q];
            }
            sRED[tid * 27 + 12] = es0;
            sRED[tid * 27 + 25] = es1;
            __syncthreads();
            if (tid < 208) {
                int v = tid % 26, chunk = tid / 26;
                float s = 0.0f;
#pragma unroll
                for (int t = 0; t < 32; ++t) s += sRED[(chunk * 32 + t) * 27 + v];
                sRED2[chunk * 26 + v] = s;
            }
            __syncthreads();
            if (tid < 26) {
                float s = 0.0f;
#pragma unroll
                for (int ch = 0; ch < 8; ++ch) s += sRED2[ch * 26 + tid];
                sACC[ap * 26 + tid] = s;
            }
            __syncthreads();
        }
        if (tid < 24) {
            int r = tid / 12, f = tid % 12;
            float inv0 = 1.0f / sACC[0 * 26 + r * 13 + 12];
            float inv1 = 1.0f / sACC[1 * 26 + r * 13 + 12];
            float inv2 = 1.0f / sACC[2 * 26 + r * 13 + 12];
            float acc1 = sW[432 + f], acc2 = sW[432 + f];
#pragma unroll
            for (int q = 0; q < 12; ++q) {
                float ga = sACC[0 * 26 + r * 13 + q] * inv0;
                float gb = sACC[1 * 26 + r * 13 + q] * inv1;
                float gc = sACC[2 * 26 + r * 13 + q] * inv2;
                acc1 += ga * sW[q * 12 + f];
                acc2 += gb * sW[144 + q * 12 + f] + gc * sW[288 + q * 12 + f];
            }
            out[(rowbase + r0 + r) * 12 + f] = fmaxf(acc1, 0.0f) + fmaxf(acc2, 0.0f);
        }
        __syncthreads();
    }
}

// ---------------- launch ----------------
extern "C" void kernel_launch(void* const* d_in, const int* in_sizes, int n_in,
                              void* d_out, int out_size) {
    const float* obs    = (const float*)d_in[0];
    const float* tf     = (const float*)d_in[1];
    const float* fc_w1  = (const float*)d_in[2];
    const float* fc_b1  = (const float*)d_in[3];
    const float* fc_w2  = (const float*)d_in[4];
    const float* fc_b2  = (const float*)d_in[5];
    const float* fc_w3  = (const float*)d_in[6];
    const float* fc_b3  = (const float*)d_in[7];
    const float* Wf     = (const float*)d_in[8];
    const float* Wb     = (const float*)d_in[9];
    const float* bvec   = (const float*)d_in[10];
    const float* li     = (const float*)d_in[11];
    const float* gs_w1  = (const float*)d_in[12];
    const float* gs_b1  = (const float*)d_in[13];
    const float* gs_w2  = (const float*)d_in[14];
    const float* gs_b2  = (const float*)d_in[15];
    const float* gt_w1  = (const float*)d_in[16];
    const float* gt_b1  = (const float*)d_in[17];
    const float* gt_w2  = (const float*)d_in[18];
    const float* gt_b2  = (const float*)d_in[19];
    const float* Bm     = (const float*)d_in[20];
    float* out = (float*)d_out;

    cudaFuncSetAttribute(conv_kernel,
                         cudaFuncAttributeMaxDynamicSharedMemorySize,
                         C_SMEM_FLOATS * sizeof(float));

    mega_kernel<<<NBLK, NTHR>>>(obs, tf, fc_w1, fc_b1, fc_w2, fc_b2,
                                fc_w3, fc_b3, li, gs_w1, gs_b1, gs_w2, gs_b2,
                                gt_w1, gt_b1, gt_w2, gt_b2, Bm, out);
    conv_kernel<<<128, 256, C_SMEM_FLOATS * sizeof(float)>>>(Wf, Wb, bvec, out);
}